// round 12
// baseline (speedup 1.0000x reference)
#include <cuda_runtime.h>
#include <cuda_bf16.h>

// CrossAttention collapse: softmax over identical key logits is exactly uniform
// -> y[b,t,:] = v[b,:] -> out[b,t,:] = ((visual@Wv+bv)@Wp + bp)[b,:].
//
//   K1 (128 blocks): per 8-wide i-chunk c: vv[b,c] = (visual@Wv+bv)[chunk],
//       then P[c][b][:] = sum_{i in c} vv[b,i]*Wp[i,:]   (no redundancy)
//   K2 (128 blocks): row-tile = bp + sum_c P[c] (8-way tree over c-groups),
//       then broadcast-store the [t-slice x c-tile] output slab.

#define C_DIM 1024
#define B_DIM 4
#define NC    128   // number of i-chunks
#define IC    8     // i per chunk

__device__ float g_P[NC][B_DIM][C_DIM];   // 2 MB partial rows

// ---------------------------------------------------------------------------
// K1 (round-10 proven version): grid = NC, block = 1024.
// Stage A: vv[b][i0..i0+7]: il = tid&7, s = tid>>3 (128-way k-split, 8 k each),
//          warp-shuffle + fixed-order smem tree.
// Stage B: thread j=tid emits P[c][b][j] = sum_q vv[b,q]*Wp[i0+q][j]
//          (loads kept in-loop: front-batching them regressed in round 11).
// ---------------------------------------------------------------------------
__global__ void __launch_bounds__(1024) k_part(
    const float* __restrict__ visual, const float* __restrict__ Wv,
    const float* __restrict__ bv,     const float* __restrict__ Wp)
{
    __shared__ float vis[B_DIM * C_DIM];          // 16 KB
    __shared__ float red[32][B_DIM][IC + 1];      // padded vs bank conflicts
    __shared__ float vvsm[B_DIM][IC];

    const int tid = threadIdx.x;
    #pragma unroll
    for (int p = 0; p < 4; ++p)
        vis[p * 1024 + tid] = visual[p * 1024 + tid];
    __syncthreads();

    const int c  = blockIdx.x;
    const int i0 = c * IC;
    const int il = tid & 7;
    const int s  = tid >> 3;       // k-slice 0..127
    const int w  = tid >> 5;       // warp 0..31
    const float* __restrict__ Wcol = Wv + i0 + il;

    float a0 = 0.f, a1 = 0.f, a2 = 0.f, a3 = 0.f;
    #pragma unroll
    for (int kk = 0; kk < 8; ++kk) {
        const int k = s * 8 + kk;
        const float wv = __ldg(Wcol + k * C_DIM);
        a0 = fmaf(vis[k],        wv, a0);
        a1 = fmaf(vis[1024 + k], wv, a1);
        a2 = fmaf(vis[2048 + k], wv, a2);
        a3 = fmaf(vis[3072 + k], wv, a3);
    }
    // intra-warp: lanes L, L+8, L+16, L+24 share il -> fixed-order reduce
    a0 += __shfl_down_sync(0xffffffffu, a0, 16);
    a1 += __shfl_down_sync(0xffffffffu, a1, 16);
    a2 += __shfl_down_sync(0xffffffffu, a2, 16);
    a3 += __shfl_down_sync(0xffffffffu, a3, 16);
    a0 += __shfl_down_sync(0xffffffffu, a0, 8);
    a1 += __shfl_down_sync(0xffffffffu, a1, 8);
    a2 += __shfl_down_sync(0xffffffffu, a2, 8);
    a3 += __shfl_down_sync(0xffffffffu, a3, 8);
    if ((tid & 31) < 8) {
        red[w][0][il] = a0; red[w][1][il] = a1;
        red[w][2][il] = a2; red[w][3][il] = a3;
    }
    __syncthreads();

    // fixed-order tree over the 32 warps (16*32=512 <= 1024 threads: valid)
    #pragma unroll
    for (int off = 16; off >= 1; off >>= 1) {
        if (tid < off * 32) {
            const int w2 = tid >> 5, r = tid & 31, b = r >> 3, il2 = r & 7;
            red[w2][b][il2] += red[w2 + off][b][il2];
        }
        __syncthreads();
    }
    if (tid < 32) {
        const int b = tid >> 3, il2 = tid & 7;
        vvsm[b][il2] = red[0][b][il2] + bv[i0 + il2];
    }
    __syncthreads();

    // Stage B: partial rows for this chunk (coalesced Wp row reads, in-loop)
    float r0 = 0.f, r1 = 0.f, r2 = 0.f, r3 = 0.f;
    #pragma unroll
    for (int q = 0; q < IC; ++q) {
        const float wp = __ldg(Wp + (i0 + q) * C_DIM + tid);
        r0 = fmaf(vvsm[0][q], wp, r0);
        r1 = fmaf(vvsm[1][q], wp, r1);
        r2 = fmaf(vvsm[2][q], wp, r2);
        r3 = fmaf(vvsm[3][q], wp, r3);
    }
    g_P[c][0][tid] = r0;
    g_P[c][1][tid] = r1;
    g_P[c][2][tid] = r2;
    g_P[c][3][tid] = r3;
}

// ---------------------------------------------------------------------------
// K2: grid = (32, 4): x = b*8 + ctile, y = t-slice of 256. block = 256.
// Thread (j4l = tid&31, cg = tid>>5): sum 16 chunk-partials (independent L2
// loads), fixed-order 3-level tree over the 8 c-groups, add bias, then 32
// fully-coalesced float4 store passes (each warp stores 512 B contiguous).
// ---------------------------------------------------------------------------
__global__ void __launch_bounds__(256) k_row_bcast(
    const float* __restrict__ bp, float4* __restrict__ out4)
{
    __shared__ float4 sm[8][32];
    __shared__ float4 rowsm[32];

    const int tid   = threadIdx.x;
    const int b     = blockIdx.x >> 3;
    const int ctile = blockIdx.x & 7;
    const int ts    = blockIdx.y;
    const int j4l   = tid & 31;
    const int cg    = tid >> 5;                // 0..7
    const int j4    = ctile * 32 + j4l;        // float4 col index 0..255

    const float4* __restrict__ P4 = reinterpret_cast<const float4*>(g_P);
    // P4 index: (c * B_DIM + b) * 256 + j4
    float4 acc = make_float4(0.f, 0.f, 0.f, 0.f);
    #pragma unroll
    for (int cc = 0; cc < 16; ++cc) {
        const int c = cg * 16 + cc;
        const float4 p = __ldg(P4 + (size_t)(c * B_DIM + b) * 256 + j4);
        acc.x += p.x; acc.y += p.y; acc.z += p.z; acc.w += p.w;
    }
    sm[cg][j4l] = acc;
    __syncthreads();

    #pragma unroll
    for (int off = 4; off >= 1; off >>= 1) {
        if (cg < off) {
            float4 a = sm[cg][j4l], bb = sm[cg + off][j4l];
            a.x += bb.x; a.y += bb.y; a.z += bb.z; a.w += bb.w;
            sm[cg][j4l] = a;
        }
        __syncthreads();
    }
    if (cg == 0) {
        float4 a = sm[0][j4l];
        const float4 bias = __ldg(reinterpret_cast<const float4*>(bp) + j4);
        a.x += bias.x; a.y += bias.y; a.z += bias.z; a.w += bias.w;
        rowsm[j4l] = a;
    }
    __syncthreads();

    // Broadcast: t in [ts*256, ts*256+256). Warp w handles t ≡ w (mod 8);
    // lanes store 32 consecutive float4 (512 B) per pass.
    const float4 val = rowsm[j4l];
    const int wrp = tid >> 5;                  // 0..7
    const size_t base = ((size_t)(b << 10) + ts * 256 + wrp) * 256 + j4;
    #pragma unroll
    for (int p = 0; p < 32; ++p)
        out4[base + (size_t)p * 8 * 256] = val;
}

extern "C" void kernel_launch(void* const* d_in, const int* in_sizes, int n_in,
                              void* d_out, int out_size)
{
    const float* visual = (const float*)d_in[1];
    const float* Wv     = (const float*)d_in[6];
    const float* bv     = (const float*)d_in[7];
    const float* Wp     = (const float*)d_in[8];
    const float* bp     = (const float*)d_in[9];

    k_part<<<NC, 1024>>>(visual, Wv, bv, Wp);
    k_row_bcast<<<dim3(32, 4), 256>>>(bp, reinterpret_cast<float4*>(d_out));
}

// round 14
// speedup vs baseline: 1.3183x; 1.3183x over previous
#include <cuda_runtime.h>
#include <cuda_bf16.h>

// CrossAttention collapse: softmax over identical key logits is exactly uniform
// -> y[b,t,:] = v[b,:] -> out[b,t,:] = ((visual@Wv+bv)@Wp + bp)[b,:].
//
// SINGLE persistent kernel (grid 128x1024, all CTAs co-resident on 148 SMs):
//   Phase 1 (block c): vv[b,chunk c] = (visual@Wv+bv)[8i], then partial rows
//            P[c][b][:] = sum_{i in c} vv[b,i]*Wp[i,:]     (no redundancy)
//   Device-wide barrier: monotonic ticket counter (never reset -> replay-safe)
//   Phase 2 (block -> (b, j-tile, t-slice)): row-tile = bp + sum_c P[c]
//            (fixed-order tree, same summation order as the 2-kernel version),
//            then broadcast-store a 32 KB output slab.

#define C_DIM 1024
#define B_DIM 4
#define NC    128   // number of i-chunks == gridDim.x
#define IC    8     // i per chunk

__device__ float g_P[NC][B_DIM][C_DIM];   // 2 MB partial rows
__device__ unsigned int g_bar = 0;        // monotonic across launches/replays

__global__ void __launch_bounds__(1024) k_fused(
    const float* __restrict__ visual, const float* __restrict__ Wv,
    const float* __restrict__ bv,     const float* __restrict__ Wp,
    const float* __restrict__ bp,     float4* __restrict__ out4)
{
    __shared__ float vis[B_DIM * C_DIM];          // 16 KB
    __shared__ float red[32][B_DIM][IC + 1];      // padded vs bank conflicts
    __shared__ float vvsm[B_DIM][IC];
    __shared__ float4 sm2[32][32];                // 16 KB phase-2 tree
    __shared__ float4 rowsm[32];

    const int tid = threadIdx.x;

    // ============================ PHASE 1 ============================
    #pragma unroll
    for (int p = 0; p < 4; ++p)
        vis[p * 1024 + tid] = visual[p * 1024 + tid];
    __syncthreads();

    {
        const int c  = blockIdx.x;
        const int i0 = c * IC;
        const int il = tid & 7;
        const int s  = tid >> 3;       // k-slice 0..127
        const int w  = tid >> 5;       // warp 0..31
        const float* __restrict__ Wcol = Wv + i0 + il;

        float a0 = 0.f, a1 = 0.f, a2 = 0.f, a3 = 0.f;
        #pragma unroll
        for (int kk = 0; kk < 8; ++kk) {
            const int k = s * 8 + kk;
            const float wv = __ldg(Wcol + k * C_DIM);
            a0 = fmaf(vis[k],        wv, a0);
            a1 = fmaf(vis[1024 + k], wv, a1);
            a2 = fmaf(vis[2048 + k], wv, a2);
            a3 = fmaf(vis[3072 + k], wv, a3);
        }
        // lanes L, L+8, L+16, L+24 share il -> fixed-order reduce
        a0 += __shfl_down_sync(0xffffffffu, a0, 16);
        a1 += __shfl_down_sync(0xffffffffu, a1, 16);
        a2 += __shfl_down_sync(0xffffffffu, a2, 16);
        a3 += __shfl_down_sync(0xffffffffu, a3, 16);
        a0 += __shfl_down_sync(0xffffffffu, a0, 8);
        a1 += __shfl_down_sync(0xffffffffu, a1, 8);
        a2 += __shfl_down_sync(0xffffffffu, a2, 8);
        a3 += __shfl_down_sync(0xffffffffu, a3, 8);
        if ((tid & 31) < 8) {
            red[w][0][il] = a0; red[w][1][il] = a1;
            red[w][2][il] = a2; red[w][3][il] = a3;
        }
        __syncthreads();

        // fixed-order tree over the 32 warps (16*32=512 <= 1024: valid)
        #pragma unroll
        for (int off = 16; off >= 1; off >>= 1) {
            if (tid < off * 32) {
                const int w2 = tid >> 5, r = tid & 31, b = r >> 3, il2 = r & 7;
                red[w2][b][il2] += red[w2 + off][b][il2];
            }
            __syncthreads();
        }
        if (tid < 32) {
            const int b = tid >> 3, il2 = tid & 7;
            vvsm[b][il2] = red[0][b][il2] + bv[i0 + il2];
        }
        __syncthreads();

        // partial rows for this chunk (coalesced Wp row reads, in-loop)
        float r0 = 0.f, r1 = 0.f, r2 = 0.f, r3 = 0.f;
        #pragma unroll
        for (int q = 0; q < IC; ++q) {
            const float wp = __ldg(Wp + (i0 + q) * C_DIM + tid);
            r0 = fmaf(vvsm[0][q], wp, r0);
            r1 = fmaf(vvsm[1][q], wp, r1);
            r2 = fmaf(vvsm[2][q], wp, r2);
            r3 = fmaf(vvsm[3][q], wp, r3);
        }
        g_P[c][0][tid] = r0;
        g_P[c][1][tid] = r1;
        g_P[c][2][tid] = r2;
        g_P[c][3][tid] = r3;
    }

    // ======================= DEVICE-WIDE BARRIER ======================
    // Release: every thread fences its g_P stores, block barrier, then tid0
    // arrives. Monotonic ticket counter -> no reset needed across replays.
    __threadfence();
    __syncthreads();
    if (tid == 0) {
        const unsigned int ticket = atomicAdd(&g_bar, 1u);
        const unsigned int target = (ticket / NC + 1u) * NC;
        while (*(volatile unsigned int*)&g_bar < target)
            __nanosleep(64);
    }
    __syncthreads();
    __threadfence();   // acquire side

    // ============================ PHASE 2 ============================
    // block -> b2 = blk>>5, jt = (blk&31)>>2 (8 j4-tiles of 32), ts = blk&3.
    {
        const int blk = blockIdx.x;
        const int b2  = blk >> 5;
        const int jt  = (blk & 31) >> 2;
        const int ts  = blk & 3;
        const int j4l = tid & 31;
        const int cg  = tid >> 5;            // 0..31, owns 4 chunks
        const int j4  = jt * 32 + j4l;       // float4 col 0..255

        const float4* __restrict__ P4 = reinterpret_cast<const float4*>(g_P);
        float4 acc = make_float4(0.f, 0.f, 0.f, 0.f);
        #pragma unroll
        for (int cc = 0; cc < 4; ++cc) {
            const int c = cg * 4 + cc;
            const float4 p = P4[(size_t)(c * B_DIM + b2) * 256 + j4];
            acc.x += p.x; acc.y += p.y; acc.z += p.z; acc.w += p.w;
        }
        sm2[cg][j4l] = acc;
        __syncthreads();

        #pragma unroll
        for (int off = 16; off >= 1; off >>= 1) {
            if (cg < off) {
                float4 a = sm2[cg][j4l], bb = sm2[cg + off][j4l];
                a.x += bb.x; a.y += bb.y; a.z += bb.z; a.w += bb.w;
                sm2[cg][j4l] = a;
            }
            __syncthreads();
        }
        if (cg == 0) {
            float4 a = sm2[0][j4l];
            const float4 bias = __ldg(reinterpret_cast<const float4*>(bp) + j4);
            a.x += bias.x; a.y += bias.y; a.z += bias.z; a.w += bias.w;
            rowsm[j4l] = a;
        }
        __syncthreads();

        // Broadcast: warp w stores t = ts*256 + w + p*32, lanes cover 32
        // consecutive float4 (512 B contiguous per warp-store).
        const float4 val  = rowsm[j4l];
        const int   trow  = tid >> 5;
        const size_t base = ((size_t)(b2 << 10) + ts * 256 + trow) * 256 + j4;
        #pragma unroll
        for (int p = 0; p < 8; ++p)
            out4[base + (size_t)p * 32 * 256] = val;
    }
}

extern "C" void kernel_launch(void* const* d_in, const int* in_sizes, int n_in,
                              void* d_out, int out_size)
{
    const float* visual = (const float*)d_in[1];
    const float* Wv     = (const float*)d_in[6];
    const float* bv     = (const float*)d_in[7];
    const float* Wp     = (const float*)d_in[8];
    const float* bp     = (const float*)d_in[9];

    k_fused<<<NC, 1024>>>(visual, Wv, bv, Wp, bp,
                          reinterpret_cast<float4*>(d_out));
}